// round 6
// baseline (speedup 1.0000x reference)
#include <cuda_runtime.h>
#include <cstdint>

// x: (512, 65536) fp32; scaling: (8, 8) fp32.
// m = 65536 is a power of two -> reference padding is a no-op and the
// forward/inverse DB4 cascade is exact perfect reconstruction, so
// denoised == x. Output = [denoised | concatenated forward coeffs].
#define ROWS    512
#define N0      65536
#define LEVELS  8
#define TPB     512
#define XCHUNK  2048
#define NCH     32

// Ring slots carry an 8-float halo prefix: slot[k] = data[base - 8 + k].
#define RSLOT   2064    // 8 halo + 2048 + 8 pad
#define P0SLOT  1040    // 8 halo + 1024 + 8 pad
#define P1SLOT  528     // 8 halo + 512  + 8 pad

#define R_OFF   0
#define P0_OFF  (4 * RSLOT)                 // 8256
#define P1_OFF  (P0_OFF + 2 * P0SLOT)       // 10336
#define A2_OFF  (P1_OFF + 4 * P1SLOT)       // 12448
#define W2_OFF  (A2_OFF + 8192)             // 20640  approx0[0..7] stash
#define S1_OFF  (W2_OFF + 8)                // 20648  approx1[0..15] stash
#define SMEM_FLOATS (S1_OFF + 16 + 8)       // 20672 floats = 82688 B

__device__ __forceinline__ void cp_async16(float* smem_dst, const float* gsrc) {
    uint32_t s = (uint32_t)__cvta_generic_to_shared(smem_dst);
    asm volatile("cp.async.cg.shared.global [%0], [%1], 16;" :: "r"(s), "l"(gsrc));
}
__device__ __forceinline__ void cp_commit() {
    asm volatile("cp.async.commit_group;");
}

// one pair of (approx, detail) outputs from a 12-float ascending window
#define PAIR_FMA(v, srf, wrf, aa0, ad0, aa1, ad1)          \
    do {                                                   \
        aa0 = ad0 = aa1 = ad1 = 0.f;                       \
        _Pragma("unroll")                                  \
        for (int j = 0; j < 8; j++) {                      \
            aa0 = fmaf(srf[j], v[j + 1], aa0);             \
            ad0 = fmaf(wrf[j], v[j + 1], ad0);             \
            aa1 = fmaf(srf[j], v[j + 3], aa1);             \
            ad1 = fmaf(wrf[j], v[j + 3], ad1);             \
        }                                                  \
    } while (0)

#define UNPACK12(b0, b1, b2, v)                            \
    do {                                                   \
        v[0]=b0.x; v[1]=b0.y; v[2] =b0.z; v[3] =b0.w;      \
        v[4]=b1.x; v[5]=b1.y; v[6] =b1.z; v[7] =b1.w;      \
        v[8]=b2.x; v[9]=b2.y; v[10]=b2.z; v[11]=b2.w;      \
    } while (0)

__global__ __launch_bounds__(TPB, 2)
void dwt_forward_kernel(const float* __restrict__ x,
                        const float* __restrict__ scaling,
                        float* __restrict__ out)
{
    extern __shared__ float sm[];
    float* R  = sm + R_OFF;
    float* P0 = sm + P0_OFF;
    float* P1 = sm + P1_OFF;
    float* A2 = sm + A2_OFF;
    float* W2 = sm + W2_OFF;
    float* S1 = sm + S1_OFF;

    const int row = blockIdx.x;
    const int tid = threadIdx.x;

    const float* xr   = x + (size_t)row * N0;
    float*       den  = out + (size_t)row * N0;                       // denoised == x
    float*       coef = out + (size_t)ROWS * N0 + (size_t)row * N0;   // coeffs

    float2* coefL0 = (float2*)coef;             // det level 0
    float2* coefL1 = (float2*)(coef + 32768);   // det level 1
    float2* coefL2 = (float2*)(coef + 49152);   // det level 2

    // Reversed filters: a[n] = sum_j sr[j]*in[2n-7+j]; wr[j] = (j odd ? s[j] : -s[j]).
    // tid<256 carries the level-1 filter in srA/wrA; tid>=256 level-2.
    float sr0[8], wr0[8], srA[8], wrA[8];
    {
        const float* sB = (tid < 256) ? (scaling + 8) : (scaling + 16);
        #pragma unroll
        for (int j = 0; j < 8; j++) {
            sr0[j] = scaling[7 - j];
            wr0[j] = (j & 1) ? scaling[j] : -scaling[j];
            srA[j] = sB[7 - j];
            wrA[j] = (j & 1) ? sB[j] : -sB[j];
        }
    }

    // Slot-0 halo prefix = circular wrap x[N0-8 .. N0-1].
    if (tid < 8) R[tid] = xr[N0 - 8 + tid];

    // Prologue: chunks 0,1,2 in flight (each chunk's halo rides in its group).
    #pragma unroll
    for (int k = 0; k < 3; k++) {
        cp_async16(R + k * RSLOT + 8 + 4 * tid, xr + k * XCHUNK + 4 * tid);
        if (k >= 1 && tid < 2)
            cp_async16(R + k * RSLOT + 4 * tid, xr + k * XCHUNK - 8 + 4 * tid);
        cp_commit();
    }

    // ---------------- Streaming: levels 0/1/2 fused
    for (int c = 0; c < NCH; c++) {
        asm volatile("cp.async.wait_group 2;");
        __syncthreads();   // sync1: x chunk c (+halo) visible; P1(c-1) visible

        // ---- level 0: all 512 threads, pair f = 512c + tid, window slot[4t..4t+11]
        const float* Rs = R + (c & 3) * RSLOT;
        const float4* win = (const float4*)Rs + tid;
        float4 b0 = win[0], b1 = win[1], b2 = win[2];
        float v[12];
        UNPACK12(b0, b1, b2, v);
        float aa0, ad0, aa1, ad1;
        PAIR_FMA(v, sr0, wr0, aa0, ad0, aa1, ad1);

        const int f = 512 * c + tid;
        coefL0[f] = make_float2(ad0, ad1);
        reinterpret_cast<float2*>(P0 + (c & 1) * P0SLOT + 8)[tid] = make_float2(aa0, aa1);
        if (tid >= 508)   // last 8 approx values -> next slot's halo prefix
            reinterpret_cast<float2*>(P0 + ((c + 1) & 1) * P0SLOT)[tid - 508] = make_float2(aa0, aa1);
        if (c == 0 && tid < 4) { W2[2 * tid] = aa0; W2[2 * tid + 1] = aa1; }

        // den chunk c via bulk store (data already in smem), one thread
        if (tid == 0) {
            asm volatile("fence.proxy.async.shared::cta;" ::: "memory");
            uint32_t saddr = (uint32_t)__cvta_generic_to_shared(Rs + 8);
            asm volatile("cp.async.bulk.global.shared::cta.bulk_group [%0], [%1], %2;"
                         :: "l"(den + (size_t)c * XCHUNK), "r"(saddr), "r"(XCHUNK * 4)
                         : "memory");
            asm volatile("cp.async.bulk.commit_group;");
            asm volatile("cp.async.bulk.wait_group.read 1;");  // chunk c-1 smem read done
        }

        __syncthreads();   // sync2: P0(c) visible; slot (c-1)&3 free for reuse

        // prefetch chunk c+3 into slot (c+3)&3 = (c-1)&3
        {
            const int k = c + 3;
            if (k < NCH) {
                cp_async16(R + (k & 3) * RSLOT + 8 + 4 * tid, xr + k * XCHUNK + 4 * tid);
                if (tid < 2)
                    cp_async16(R + (k & 3) * RSLOT + 4 * tid, xr + k * XCHUNK - 8 + 4 * tid);
            }
            cp_commit();   // unconditional: keeps per-thread group counts aligned
        }

        if (tid < 256) {
            // ---- level 1: pair g = 256c + tid from P0 slot (c&1)
            if (!(c == 0 && tid < 2)) {            // wrap pairs deferred
                const float4* wq = (const float4*)(P0 + (c & 1) * P0SLOT) + tid;
                float4 q0 = wq[0], q1 = wq[1], q2 = wq[2];
                float q[12];
                UNPACK12(q0, q1, q2, q);
                float ba0, bd0, ba1, bd1;
                PAIR_FMA(q, srA, wrA, ba0, bd0, ba1, bd1);
                const int g = 256 * c + tid;
                coefL1[g] = make_float2(bd0, bd1);
                reinterpret_cast<float2*>(P1 + (c & 3) * P1SLOT + 8)[tid] = make_float2(ba0, ba1);
                if (tid >= 252)
                    reinterpret_cast<float2*>(P1 + ((c + 1) & 3) * P1SLOT)[tid - 252] = make_float2(ba0, ba1);
                if (c == 0 && tid < 8) { S1[2 * tid] = ba0; S1[2 * tid + 1] = ba1; }
            }
        } else if (tid < 384 && c >= 1) {
            // ---- level 2 (lag 1): pair u = 128(c-1) + t from P1 slot ((c-1)&3)
            const int t = tid - 256;
            if (!(c == 1 && t < 4)) {              // wrap-adjacent pairs deferred
                const float4* wq = (const float4*)(P1 + ((c - 1) & 3) * P1SLOT) + t;
                float4 q0 = wq[0], q1 = wq[1], q2 = wq[2];
                float q[12];
                UNPACK12(q0, q1, q2, q);
                float ca0, cd0, ca1, cd1;
                PAIR_FMA(q, srA, wrA, ca0, cd0, ca1, cd1);
                const int u = 128 * (c - 1) + t;
                coefL2[u] = make_float2(cd0, cd1);
                reinterpret_cast<float2*>(A2)[u] = make_float2(ca0, ca1);
            }
        }
    }
    if (tid == 0) asm volatile("cp.async.bulk.wait_group 0;");  // den fully stored
    __syncthreads();   // P0(31), P1(31) visible

    // ---------------- Epilogue 1: deferred level-1 wrap pairs g = 0,1
    if (tid < 2) {
        float v[12];
        #pragma unroll
        for (int k = 0; k < 12; k++) {
            int idx = 4 * tid - 8 + k;             // approx0 index
            v[k] = (idx < 0) ? P0[P0SLOT + 1032 + idx] : W2[idx];   // slot1 tail | stash
        }
        float aa0, ad0, aa1, ad1;
        PAIR_FMA(v, srA, wrA, aa0, ad0, aa1, ad1);  // tid<2 holds L1 filter
        coefL1[tid] = make_float2(ad0, ad1);
        S1[2 * tid]     = aa0;                      // approx1[0..3]
        S1[2 * tid + 1] = aa1;
    }
    __syncthreads();

    // ---------------- Epilogue 2: level-2 trailing chunk 31 + deferred wrap pairs
    if (tid >= 256 && tid < 384) {                  // u = 3968..4095 from P1 slot 3
        const int t = tid - 256;
        const float4* wq = (const float4*)(P1 + 3 * P1SLOT) + t;
        float4 q0 = wq[0], q1 = wq[1], q2 = wq[2];
        float q[12];
        UNPACK12(q0, q1, q2, q);
        float ca0, cd0, ca1, cd1;
        PAIR_FMA(q, srA, wrA, ca0, cd0, ca1, cd1);  // L2 filter
        const int u = 3968 + t;
        coefL2[u] = make_float2(cd0, cd1);
        reinterpret_cast<float2*>(A2)[u] = make_float2(ca0, ca1);
    }
    if (tid >= 508) {                               // deferred u = 0..3
        const int u = tid - 508;
        float v[12];
        #pragma unroll
        for (int k = 0; k < 12; k++) {
            int idx = 4 * u - 8 + k;               // approx1 index
            v[k] = (idx < 0) ? P1[3 * P1SLOT + 520 + idx] : S1[idx];
        }
        float ca0, cd0, ca1, cd1;
        PAIR_FMA(v, srA, wrA, ca0, cd0, ca1, cd1);  // tid>=508 holds L2 filter
        coefL2[u] = make_float2(cd0, cd1);
        reinterpret_cast<float2*>(A2)[u] = make_float2(ca0, ca1);
    }
    __syncthreads();

    // ---------------- Levels 3..7 in shared memory (A2 <-> R ping-pong)
    float* cur = A2;
    int nin = 8192;
    for (int l = 3; l < LEVELS; l++) {
        const float* s0 = scaling + 8 * l;
        float srl[8], wrl[8];
        #pragma unroll
        for (int j = 0; j < 8; j++) {
            srl[j] = s0[7 - j];
            wrl[j] = (j & 1) ? s0[j] : -s0[j];
        }
        const int nout   = nin >> 1;
        const int npairs = nout >> 1;
        float* ob = (cur == A2) ? R : A2;
        const int off = N0 - (N0 >> l);

        for (int u = tid; u < npairs; u += TPB) {
            float v2[12];
            if (u >= 2) {
                const float4* p = (const float4*)cur + (u - 2);
                float4 c0 = p[0], c1 = p[1], c2 = p[2];
                UNPACK12(c0, c1, c2, v2);
            } else {
                #pragma unroll
                for (int k = 0; k < 12; k++) {
                    int idx = 4 * u - 8 + k;
                    if (idx < 0) idx += nin;
                    v2[k] = cur[idx];
                }
            }
            float aa0, ad0, aa1, ad1;
            PAIR_FMA(v2, srl, wrl, aa0, ad0, aa1, ad1);
            reinterpret_cast<float2*>(coef + off)[u] = make_float2(ad0, ad1);
            reinterpret_cast<float2*>(ob)[u]         = make_float2(aa0, aa1);
        }
        __syncthreads();
        cur = ob;
        nin = nout;
    }

    // Final approx (256 samples).
    if (tid < (N0 >> LEVELS))
        coef[N0 - (N0 >> LEVELS) + tid] = cur[tid];
}

extern "C" void kernel_launch(void* const* d_in, const int* in_sizes, int n_in,
                              void* d_out, int out_size)
{
    const float* x       = (const float*)d_in[0];
    const float* scaling = (const float*)d_in[1];
    float*       out     = (float*)d_out;

    (void)in_sizes; (void)n_in; (void)out_size;

    cudaFuncSetAttribute(dwt_forward_kernel,
                         cudaFuncAttributeMaxDynamicSharedMemorySize,
                         SMEM_FLOATS * (int)sizeof(float));

    dwt_forward_kernel<<<ROWS, TPB, SMEM_FLOATS * (int)sizeof(float)>>>(x, scaling, out);
}